// round 16
// baseline (speedup 1.0000x reference)
#include <cuda_runtime.h>
#include <cuda_fp16.h>
#include <cstdint>

// ---------------- problem constants ----------------
#define C_IN   256
#define C_OUT  256
#define PIXN   16384          // 64*256 pixels per (tensor, batch)
#define HOUTN  768
#define WwN    256

// ---------------- tiling ----------------
// CTA: 128 out-ch x 128 pixels, 4 warps, warp tile 64x64. K chunks of 16 (1 x k16).
// fp16 m16n8k16 HMMA with fp16 accumulate. 4 CTAs/SM (16 warps).
// W: cp.async 3-stage (pre-packed fragment quads).
// X: producer LDG fp32 -> cvt f16x2 -> STS, 2 chunks ahead, 3 fp16 stages.
#define KB      16
#define NCHUNK  16
#define RPXH    136           // X row stride in u32(f16x2): banks 8*tig+gid -> conflict-free
#define W_STAGE 4096          // fp16 fragment-packed W chunk: 256 uint4 (128m x 16k)
#define X_STAGE (8*RPXH*4)    // 8 k2-rows x 136 u32 = 4352 B
#define STAGE_B (W_STAGE + X_STAGE)     // 8448
#define NSTAGE  3
#define SMEM_BYTES (NSTAGE * STAGE_B)   // 25344 -> 4 CTAs/SM (reg-capped at 128)

// W fragment quads, fp16x2: uint4 index = ((ch*2+cht)*8 + mb)*32 + lane
__device__ uint4 g_Wh[NCHUNK * 2 * 8 * 32];   // 8192 uint4 = 128KB

struct XPtrs { const float* p[12]; };

__device__ __forceinline__ uint32_t pack_h2(float lo, float hi) {
    uint32_t r;
    asm("cvt.rn.f16x2.f32 %0, %1, %2;" : "=r"(r) : "f"(hi), "f"(lo));
    return r;
}
// fp16-accumulate HMMA: D(f16x2 pair) = A*B + D
__device__ __forceinline__ void mma_f16acc(uint32_t& d0, uint32_t& d1,
                                           uint32_t a0, uint32_t a1, uint32_t a2, uint32_t a3,
                                           uint32_t b0, uint32_t b1) {
    asm volatile(
        "mma.sync.aligned.m16n8k16.row.col.f16.f16.f16.f16 "
        "{%0,%1},{%2,%3,%4,%5},{%6,%7},{%0,%1};"
        : "+r"(d0), "+r"(d1)
        : "r"(a0), "r"(a1), "r"(a2), "r"(a3), "r"(b0), "r"(b1));
}
__device__ __forceinline__ void cp16(void* s, const void* g) {
    uint32_t sa = (uint32_t)__cvta_generic_to_shared(s);
    asm volatile("cp.async.cg.shared.global [%0], [%1], 16;\n" :: "r"(sa), "l"(g));
}

// ---- pre-kernel: pack W[c][o] -> fp16 fragment quads (k16 chunks) ----
// quad u: lane=u&31, mb=(u>>5)&7, cht=(u>>8)&1, ch=u>>9
// a0={W[k][m],W[k+1][m]} a1={..m+8} a2={W[k+8][m],W[k+9][m]} a3={..m+8}, k=ch*16+2*tig
__global__ void wpack_kernel(const float* __restrict__ W) {
    int u    = blockIdx.x * 256 + threadIdx.x;    // 0..8191
    int lane = u & 31;
    int mb   = (u >> 5) & 7;
    int cht  = (u >> 8) & 1;
    int ch   = u >> 9;
    int gid = lane >> 2, tig = lane & 3;
    int m = cht * 128 + mb * 16 + gid;
    int k = ch * KB + 2 * tig;
    uint4 q;
    q.x = pack_h2(W[k * C_OUT + m],           W[(k + 1) * C_OUT + m]);
    q.y = pack_h2(W[k * C_OUT + m + 8],       W[(k + 1) * C_OUT + m + 8]);
    q.z = pack_h2(W[(k + 8) * C_OUT + m],     W[(k + 9) * C_OUT + m]);
    q.w = pack_h2(W[(k + 8) * C_OUT + m + 8], W[(k + 9) * C_OUT + m + 8]);
    g_Wh[u] = q;
}

// ---- main kernel ----
__global__ void __launch_bounds__(128, 4)
conv_interleave_kernel(XPtrs xs, const float* __restrict__ bg, float* __restrict__ out)
{
    extern __shared__ char smem[];

    const int tid  = threadIdx.x;     // 0..127
    const int lane = tid & 31;
    const int warp = tid >> 5;        // 0..3
    const int gid  = lane >> 2;
    const int tig  = lane & 3;

    // pair out-channel halves of one pixel tile adjacently -> co-resident, X hits L2
    const int bx  = blockIdx.x;       // 0..255
    const int p0  = (bx >> 1) * 128;
    const int cht = bx & 1;
    const int z   = blockIdx.y;       // 0..23
    const int ii  = z >> 1;
    const int bb  = z & 1;
    const float* Xg = xs.p[ii] + (size_t)bb * (C_IN * PIXN);

    const int warp_m = (warp >> 1) * 64;    // local out-channel base (0 or 64)
    const int wmb    = (warp >> 1) * 4;     // local m16-block base
    const int warp_n = (warp & 1) * 64;     // pixel base (0 or 64)

    // X producer geometry: k2-pair row kp = tid>>4 (0..7), px group g = tid&15
    const int kp = tid >> 4;
    const int gX = tid & 15;

    // fp16x2 accumulators: da[mb][nb][0] = rows gid cols {2tig,2tig+1}; [1] = rows gid+8
    uint32_t da[4][8][2];
    #pragma unroll
    for (int mb = 0; mb < 4; ++mb)
        #pragma unroll
        for (int nb = 0; nb < 8; ++nb) {
            da[mb][nb][0] = 0u;
            da[mb][nb][1] = 0u;
        }

    auto load_W = [&](int ch) {                  // cp.async, pre-packed quads
        char* wdst = smem + (ch % NSTAGE) * STAGE_B;
        const uint4* wsrc = g_Wh + (ch * 2 + cht) * 256;
        cp16(wdst + tid * 16,                wsrc + tid);
        cp16(wdst + (128 + tid) * 16,        wsrc + 128 + tid);
        asm volatile("cp.async.commit_group;");
    };
    // X: LDG fp32 rows (2kp, 2kp+1) px gX*4 + 64j  -> pack -> STS f16x2
    auto load_X = [&](int ch) {
        const float* baseA = Xg + (size_t)(ch * KB + 2 * kp) * PIXN + p0 + gX * 4;
        const float* baseB = baseA + PIXN;
        float4 ra[2], rb[2];
        #pragma unroll
        for (int j = 0; j < 2; ++j) {
            ra[j] = *(const float4*)(baseA + 64 * j);
            rb[j] = *(const float4*)(baseB + 64 * j);
        }
        uint32_t* xdst = (uint32_t*)(smem + (ch % NSTAGE) * STAGE_B + W_STAGE);
        #pragma unroll
        for (int j = 0; j < 2; ++j) {
            uint4 q;
            q.x = pack_h2(ra[j].x, rb[j].x);
            q.y = pack_h2(ra[j].y, rb[j].y);
            q.z = pack_h2(ra[j].z, rb[j].z);
            q.w = pack_h2(ra[j].w, rb[j].w);
            *(uint4*)(xdst + kp * RPXH + gX * 4 + 64 * j) = q;
        }
    };

    // ---- prologue: W stages 0,1 in flight; X chunks 0,1 packed ----
    load_W(0);
    load_W(1);
    load_X(0);
    load_X(1);

    // ---- mainloop ----
    #pragma unroll 1
    for (int ch = 0; ch < NCHUNK; ++ch) {
        if (ch == NCHUNK - 1) asm volatile("cp.async.wait_group 0;");
        else                  asm volatile("cp.async.wait_group 1;");
        __syncthreads();   // W(ch)+X(ch) resident & visible; all warps done with ch-1,
                           // so stage (ch+2)%3 (== (ch-1)%3) is free to refill

        if (ch + 2 < NCHUNK) {
            load_W(ch + 2);
            load_X(ch + 2);
        }

        const uint4*    Wf = (const uint4*)(smem + (ch % NSTAGE) * STAGE_B);
        const uint32_t* Xh = (const uint32_t*)(smem + (ch % NSTAGE) * STAGE_B + W_STAGE);

        // A fragments: one LDS.128 per m16-block (full k16), pre-packed fp16
        uint4 aq[4];
        #pragma unroll
        for (int mb = 0; mb < 4; ++mb)
            aq[mb] = Wf[(wmb + mb) * 32 + lane];

        // B fragments: single LDS.32 each (fp16x2 k-pairs; banks 8*tig+gid -> conflict-free)
        uint32_t bt[16];
        #pragma unroll
        for (int nb = 0; nb < 8; ++nb) {
            const int n = warp_n + nb * 8 + gid;
            bt[2 * nb]     = Xh[tig * RPXH + n];            // k = 2tig, 2tig+1
            bt[2 * nb + 1] = Xh[(tig + 4) * RPXH + n];      // k = 2tig+8, 2tig+9
        }

        #pragma unroll
        for (int mb = 0; mb < 4; ++mb) {
            #pragma unroll
            for (int nb = 0; nb < 8; ++nb)
                mma_f16acc(da[mb][nb][0], da[mb][nb][1],
                           aq[mb].x, aq[mb].y, aq[mb].z, aq[mb].w,
                           bt[2 * nb], bt[2 * nb + 1]);
        }
    }

    // ---- epilogue: unpack fp16 accum, add fp32 bias*count, interleaved scatter ----
    #pragma unroll
    for (int mb = 0; mb < 4; ++mb) {
        const int o = cht * 128 + warp_m + mb * 16 + gid;
        const float bv0 = __ldg(bg + o);
        const float bv1 = __ldg(bg + o + 8);
        #pragma unroll
        for (int nb = 0; nb < 8; ++nb) {
            const int p = p0 + warp_n + nb * 8 + 2 * tig;
            const int h = p >> 8;
            const int w = p & 255;
            const int r = 12 * h + ii;
            const int cnt = min(11, r) - max(0, r - (HOUTN - 12)) + 1;
            const float fc = (float)cnt;
            const float bias0 = bv0 * fc;
            const float bias1 = bv1 * fc;
            const float2 f0 = __half22float2(*reinterpret_cast<__half2*>(&da[mb][nb][0]));
            const float2 f1 = __half22float2(*reinterpret_cast<__half2*>(&da[mb][nb][1]));
            const size_t base = ((size_t)(bb * C_OUT + o) * HOUTN + r) * WwN + w;
            float2 v0 = make_float2(f0.x + bias0, f0.y + bias0);
            float2 v1 = make_float2(f1.x + bias1, f1.y + bias1);
            *reinterpret_cast<float2*>(out + base) = v0;
            *reinterpret_cast<float2*>(out + base + (size_t)8 * HOUTN * WwN) = v1;
        }
    }
}

extern "C" void kernel_launch(void* const* d_in, const int* in_sizes, int n_in,
                              void* d_out, int out_size)
{
    (void)in_sizes; (void)n_in; (void)out_size;

    XPtrs xs;
    for (int i = 0; i < 12; ++i) xs.p[i] = (const float*)d_in[i];
    const float* W = (const float*)d_in[12];
    const float* b = (const float*)d_in[13];
    float* out = (float*)d_out;

    wpack_kernel<<<32, 256>>>(W);

    cudaFuncSetAttribute(conv_interleave_kernel,
                         cudaFuncAttributeMaxDynamicSharedMemorySize, SMEM_BYTES);
    dim3 grid(256, 24, 1);   // (pixel-tile, ch-half) pairs x 24
    conv_interleave_kernel<<<grid, 128, SMEM_BYTES>>>(xs, b, out);
}

// round 17
// speedup vs baseline: 1.2701x; 1.2701x over previous
#include <cuda_runtime.h>
#include <cuda_fp16.h>
#include <cstdint>

// ---------------- problem constants ----------------
#define C_IN   256
#define C_OUT  256
#define PIXN   16384          // 64*256 pixels per (tensor, batch)
#define HOUTN  768
#define WwN    256

// ---------------- tiling ----------------
// CTA: 128 out-ch x 128 pixels, 4 warps, warp tile 64x64. K chunks of 16 (1 x k16).
// fp16 m16n8k16 HMMA with fp16 accumulate. 4 CTAs/SM (16 warps).
// All-cp.async, 4 stages, prefetch depth 2 (wait_group 2).
#define KB      16
#define NCHUNK  16
#define RPXF    132           // X row stride floats: banks 8*tig+gid -> conflict-free
#define W_STAGE 4096          // fp16 fragment-packed W chunk: 256 uint4 (128m x 16k)
#define X_STAGE (KB*RPXF*4)   // 16 rows x 132 floats = 8448 B
#define STAGE_B (W_STAGE + X_STAGE)     // 12544
#define NSTAGE  4
#define SMEM_BYTES (NSTAGE * STAGE_B)   // 50176 -> 4 CTAs/SM (reg-capped at 128)

// W fragment quads, fp16x2: uint4 index = ((ch*2+cht)*8 + mb)*32 + lane
__device__ uint4 g_Wh[NCHUNK * 2 * 8 * 32];   // 8192 uint4 = 128KB

struct XPtrs { const float* p[12]; };

__device__ __forceinline__ uint32_t pack_h2(float lo, float hi) {
    uint32_t r;
    asm("cvt.rn.f16x2.f32 %0, %1, %2;" : "=r"(r) : "f"(hi), "f"(lo));
    return r;
}
// fp16-accumulate HMMA: D(f16x2 pair) = A*B + D
__device__ __forceinline__ void mma_f16acc(uint32_t& d0, uint32_t& d1,
                                           uint32_t a0, uint32_t a1, uint32_t a2, uint32_t a3,
                                           uint32_t b0, uint32_t b1) {
    asm volatile(
        "mma.sync.aligned.m16n8k16.row.col.f16.f16.f16.f16 "
        "{%0,%1},{%2,%3,%4,%5},{%6,%7},{%0,%1};"
        : "+r"(d0), "+r"(d1)
        : "r"(a0), "r"(a1), "r"(a2), "r"(a3), "r"(b0), "r"(b1));
}
__device__ __forceinline__ void cp16(void* s, const void* g) {
    uint32_t sa = (uint32_t)__cvta_generic_to_shared(s);
    asm volatile("cp.async.cg.shared.global [%0], [%1], 16;\n" :: "r"(sa), "l"(g));
}

// ---- pre-kernel: pack W[c][o] -> fp16 fragment quads (k16 chunks) ----
// quad u: lane=u&31, mb=(u>>5)&7, cht=(u>>8)&1, ch=u>>9
// a0={W[k][m],W[k+1][m]} a1={..m+8} a2={W[k+8][m],W[k+9][m]} a3={..m+8}, k=ch*16+2*tig
__global__ void wpack_kernel(const float* __restrict__ W) {
    int u    = blockIdx.x * 256 + threadIdx.x;    // 0..8191
    int lane = u & 31;
    int mb   = (u >> 5) & 7;
    int cht  = (u >> 8) & 1;
    int ch   = u >> 9;
    int gid = lane >> 2, tig = lane & 3;
    int m = cht * 128 + mb * 16 + gid;
    int k = ch * KB + 2 * tig;
    uint4 q;
    q.x = pack_h2(W[k * C_OUT + m],           W[(k + 1) * C_OUT + m]);
    q.y = pack_h2(W[k * C_OUT + m + 8],       W[(k + 1) * C_OUT + m + 8]);
    q.z = pack_h2(W[(k + 8) * C_OUT + m],     W[(k + 9) * C_OUT + m]);
    q.w = pack_h2(W[(k + 8) * C_OUT + m + 8], W[(k + 9) * C_OUT + m + 8]);
    g_Wh[u] = q;
}

// ---- main kernel ----
__global__ void __launch_bounds__(128, 4)
conv_interleave_kernel(XPtrs xs, const float* __restrict__ bg, float* __restrict__ out)
{
    extern __shared__ char smem[];

    const int tid  = threadIdx.x;     // 0..127
    const int lane = tid & 31;
    const int warp = tid >> 5;        // 0..3
    const int gid  = lane >> 2;
    const int tig  = lane & 3;

    // pair out-channel halves of one pixel tile adjacently -> co-resident, X hits L2
    const int bx  = blockIdx.x;       // 0..255
    const int p0  = (bx >> 1) * 128;
    const int cht = bx & 1;
    const int z   = blockIdx.y;       // 0..23
    const int ii  = z >> 1;
    const int bb  = z & 1;
    const float* Xg = xs.p[ii] + (size_t)bb * (C_IN * PIXN);

    const int warp_m = (warp >> 1) * 64;    // local out-channel base (0 or 64)
    const int wmb    = (warp >> 1) * 4;     // local m16-block base
    const int warp_n = (warp & 1) * 64;     // pixel base (0 or 64)

    // fp16x2 accumulators: da[mb][nb][0] = rows gid cols {2tig,2tig+1}; [1] = rows gid+8
    uint32_t da[4][8][2];
    #pragma unroll
    for (int mb = 0; mb < 4; ++mb)
        #pragma unroll
        for (int nb = 0; nb < 8; ++nb) {
            da[mb][nb][0] = 0u;
            da[mb][nb][1] = 0u;
        }

    // ---- async stage loader: W quads + X fp32, one commit group per chunk ----
    auto load_stage = [&](int ch) {
        char* wdst = smem + (ch % NSTAGE) * STAGE_B;
        char* xdst = wdst + W_STAGE;
        const uint4* wsrc = g_Wh + (ch * 2 + cht) * 256;
        #pragma unroll
        for (int it = 0; it < 2; ++it)               // W: 256 x 16B
            cp16(wdst + (it * 128 + tid) * 16, wsrc + it * 128 + tid);
        #pragma unroll
        for (int it = 0; it < 4; ++it) {             // X: 16 rows x 512B (row stride 528B)
            int idx = it * 128 + tid;                 // 0..511
            int row = idx >> 5, seg = idx & 31;
            cp16(xdst + row * (RPXF * 4) + seg * 16,
                 Xg + (size_t)(ch * KB + row) * PIXN + p0 + seg * 4);
        }
        asm volatile("cp.async.commit_group;");
    };

    // ---- prologue: fill 3 of 4 stages ----
    load_stage(0);
    load_stage(1);
    load_stage(2);

    // ---- mainloop ----
    #pragma unroll 1
    for (int ch = 0; ch < NCHUNK; ++ch) {
        const int rem = NCHUNK - 1 - ch;              // chunks still to be loaded after this
        if (rem >= 2)      asm volatile("cp.async.wait_group 2;");
        else if (rem == 1) asm volatile("cp.async.wait_group 1;");
        else               asm volatile("cp.async.wait_group 0;");
        __syncthreads();   // chunk ch resident; all warps done with chunk ch-1,
                           // whose stage (ch-1)%4 == (ch+3)%4 is the one refilled below

        if (ch + 3 < NCHUNK) load_stage(ch + 3);

        const uint4* Wf = (const uint4*)(smem + (ch % NSTAGE) * STAGE_B);
        const float* Xs = (const float*)(smem + (ch % NSTAGE) * STAGE_B + W_STAGE);

        // A fragments: one LDS.128 per m16-block (full k16), pre-packed fp16
        uint4 aq[4];
        #pragma unroll
        for (int mb = 0; mb < 4; ++mb)
            aq[mb] = Wf[(wmb + mb) * 32 + lane];

        // B fragments: fp32 LDS pairs -> fp16x2 (conflict-free: banks 8*tig+gid)
        const int k0 = 2 * tig;
        uint32_t bt[16];
        #pragma unroll
        for (int nb = 0; nb < 8; ++nb) {
            const int n = warp_n + nb * 8 + gid;
            bt[2 * nb]     = pack_h2(Xs[k0 * RPXF + n],       Xs[(k0 + 1) * RPXF + n]);
            bt[2 * nb + 1] = pack_h2(Xs[(k0 + 8) * RPXF + n], Xs[(k0 + 9) * RPXF + n]);
        }

        #pragma unroll
        for (int mb = 0; mb < 4; ++mb) {
            #pragma unroll
            for (int nb = 0; nb < 8; ++nb)
                mma_f16acc(da[mb][nb][0], da[mb][nb][1],
                           aq[mb].x, aq[mb].y, aq[mb].z, aq[mb].w,
                           bt[2 * nb], bt[2 * nb + 1]);
        }
    }

    // ---- epilogue: unpack fp16 accum, add fp32 bias*count, interleaved scatter ----
    #pragma unroll
    for (int mb = 0; mb < 4; ++mb) {
        const int o = cht * 128 + warp_m + mb * 16 + gid;
        const float bv0 = __ldg(bg + o);
        const float bv1 = __ldg(bg + o + 8);
        #pragma unroll
        for (int nb = 0; nb < 8; ++nb) {
            const int p = p0 + warp_n + nb * 8 + 2 * tig;
            const int h = p >> 8;
            const int w = p & 255;
            const int r = 12 * h + ii;
            const int cnt = min(11, r) - max(0, r - (HOUTN - 12)) + 1;
            const float fc = (float)cnt;
            const float bias0 = bv0 * fc;
            const float bias1 = bv1 * fc;
            const float2 f0 = __half22float2(*reinterpret_cast<__half2*>(&da[mb][nb][0]));
            const float2 f1 = __half22float2(*reinterpret_cast<__half2*>(&da[mb][nb][1]));
            const size_t base = ((size_t)(bb * C_OUT + o) * HOUTN + r) * WwN + w;
            float2 v0 = make_float2(f0.x + bias0, f0.y + bias0);
            float2 v1 = make_float2(f1.x + bias1, f1.y + bias1);
            *reinterpret_cast<float2*>(out + base) = v0;
            *reinterpret_cast<float2*>(out + base + (size_t)8 * HOUTN * WwN) = v1;
        }
    }
}

extern "C" void kernel_launch(void* const* d_in, const int* in_sizes, int n_in,
                              void* d_out, int out_size)
{
    (void)in_sizes; (void)n_in; (void)out_size;

    XPtrs xs;
    for (int i = 0; i < 12; ++i) xs.p[i] = (const float*)d_in[i];
    const float* W = (const float*)d_in[12];
    const float* b = (const float*)d_in[13];
    float* out = (float*)d_out;

    wpack_kernel<<<32, 256>>>(W);

    cudaFuncSetAttribute(conv_interleave_kernel,
                         cudaFuncAttributeMaxDynamicSharedMemorySize, SMEM_BYTES);
    dim3 grid(256, 24, 1);   // (pixel-tile, ch-half) pairs x 24
    conv_interleave_kernel<<<grid, 128, SMEM_BYTES>>>(xs, b, out);
}